// round 11
// baseline (speedup 1.0000x reference)
#include <cuda_runtime.h>
#include <cuda_bf16.h>
#include <stdint.h>

// Shapes (fixed by the problem)
#define NB   4
#define NN   1024
#define HH   256
#define HD2  128
#define TT   12
#define MTOT (NB * NN)   // 4096

// Scratch (static device allocations are allowed)
__device__ __align__(256) float g_H1o[MTOT * HH];   // relu(X@W1o+b1o)
__device__ __align__(256) float g_H1d[MTOT * HH];   // relu(X@W1d+b1d)
__device__ __align__(256) float g_Wf [HH * HD2];    // W2o @ Wb
__device__ __align__(256) float g_bf [HD2];         // b2o @ Wb
// bf16 hi/lo splits consumed by the tensor-core scores kernel
__device__ __align__(256) __nv_bfloat16 g_OWhi[MTOT * HD2];
__device__ __align__(256) __nv_bfloat16 g_OWlo[MTOT * HD2];
__device__ __align__(256) __nv_bfloat16 g_Dhi [MTOT * HD2];
__device__ __align__(256) __nv_bfloat16 g_Dlo [MTOT * HD2];

// ===========================================================================
// Warp-level tensor-core helpers (base ISA: compile clean at compute_103)
// ===========================================================================
__device__ __forceinline__ uint32_t smem_u32(const void* p) {
    uint32_t a;
    asm("{ .reg .u64 t; cvta.to.shared.u64 t, %1; cvt.u32.u64 %0, t; }"
        : "=r"(a) : "l"(p));
    return a;
}

__device__ __forceinline__ void ldsm_x4(uint32_t* r, uint32_t addr) {
    asm volatile("ldmatrix.sync.aligned.m8n8.x4.shared.b16 {%0,%1,%2,%3}, [%4];"
                 : "=r"(r[0]), "=r"(r[1]), "=r"(r[2]), "=r"(r[3]) : "r"(addr));
}

// D(16x8,f32) += A(16x16 row-major bf16) * B(16x8 col-major bf16)
__device__ __forceinline__ void mma16816(float* d, const uint32_t* a, const uint32_t* b) {
    asm volatile(
        "mma.sync.aligned.m16n8k16.row.col.f32.bf16.bf16.f32 "
        "{%0,%1,%2,%3}, {%4,%5,%6,%7}, {%8,%9}, {%0,%1,%2,%3};"
        : "+f"(d[0]), "+f"(d[1]), "+f"(d[2]), "+f"(d[3])
        : "r"(a[0]), "r"(a[1]), "r"(a[2]), "r"(a[3]), "r"(b[0]), "r"(b[1]));
}

__device__ __forceinline__ unsigned pack_bf2(float a, float b) {
    __nv_bfloat162 t = __floats2bfloat162_rn(a, b);
    return ((unsigned)__bfloat16_as_ushort(t.y) << 16) | (unsigned)__bfloat16_as_ushort(t.x);
}

// ===========================================================================
// Fold Wb into the second o-layer:  Wf = W2o @ Wb, bf = b2o @ Wb
// ===========================================================================
__global__ void fuse_w_kernel(const float* __restrict__ W2o,
                              const float* __restrict__ b2o,
                              const float* __restrict__ Wb)
{
    int n = threadIdx.x;   // 0..127
    int k = blockIdx.x;    // 0..255
    float s = 0.f;
#pragma unroll 8
    for (int l = 0; l < HD2; l++)
        s = fmaf(W2o[k * HD2 + l], Wb[l * HD2 + n], s);
    g_Wf[k * HD2 + n] = s;
    if (k == 0) {
        float s2 = 0.f;
#pragma unroll 8
        for (int l = 0; l < HD2; l++)
            s2 = fmaf(b2o[l], Wb[l * HD2 + n], s2);
        g_bf[n] = s2;
    }
}

// ===========================================================================
// Stage 0 SIMT GEMM: H1{o,d} = relu(X @ W1{o,d} + b1{o,d}), M=4096 N=256 K=256
// tiles 128x64x16, thread tile 8x4, 256 threads, z selects o/d
// ===========================================================================
__global__ __launch_bounds__(256)
void gemm_stage0_kernel(const float* __restrict__ X,
                        const float* __restrict__ W1o, const float* __restrict__ W1d,
                        const float* __restrict__ b1o, const float* __restrict__ b1d)
{
    const int K = HH, N = HH;
    const int z = blockIdx.z;
    const float* A    = X;
    const float* Bm   = z ? W1d : W1o;
    const float* bias = z ? b1d : b1o;
    float* C          = z ? g_H1d : g_H1o;

    __shared__ float As[16][132];
    __shared__ float Bs[16][64];

    const int tid = threadIdx.x;
    const int tx  = tid & 15;
    const int ty  = tid >> 4;
    const int m0  = blockIdx.y * 128;
    const int n0  = blockIdx.x * 64;
    const int ar  = tid >> 2;
    const int ac  = (tid & 3) << 2;
    const int br  = tid >> 4;
    const int bc  = (tid & 15) << 2;

    const float* Ap0 = A + (size_t)(m0 + ar) * K;
    const float* Ap1 = A + (size_t)(m0 + ar + 64) * K;

    float acc[8][4];
#pragma unroll
    for (int i = 0; i < 8; i++)
#pragma unroll
        for (int j = 0; j < 4; j++) acc[i][j] = 0.f;

    for (int k0 = 0; k0 < K; k0 += 16) {
        float4 a0v = *(const float4*)(Ap0 + k0 + ac);
        float4 a1v = *(const float4*)(Ap1 + k0 + ac);
        float4 bv  = *(const float4*)(Bm + (size_t)(k0 + br) * N + n0 + bc);
        __syncthreads();
        As[ac + 0][ar] = a0v.x; As[ac + 1][ar] = a0v.y;
        As[ac + 2][ar] = a0v.z; As[ac + 3][ar] = a0v.w;
        As[ac + 0][ar + 64] = a1v.x; As[ac + 1][ar + 64] = a1v.y;
        As[ac + 2][ar + 64] = a1v.z; As[ac + 3][ar + 64] = a1v.w;
        *(float4*)&Bs[br][bc] = bv;
        __syncthreads();
#pragma unroll
        for (int k = 0; k < 16; k++) {
            float4 aA = *(const float4*)&As[k][ty * 8];
            float4 aB = *(const float4*)&As[k][ty * 8 + 4];
            float4 b4 = *(const float4*)&Bs[k][tx * 4];
            float av[8] = {aA.x, aA.y, aA.z, aA.w, aB.x, aB.y, aB.z, aB.w};
            float bw[4] = {b4.x, b4.y, b4.z, b4.w};
#pragma unroll
            for (int i = 0; i < 8; i++)
#pragma unroll
                for (int j = 0; j < 4; j++)
                    acc[i][j] = fmaf(av[i], bw[j], acc[i][j]);
        }
    }

    float4 bias4 = *(const float4*)(bias + n0 + tx * 4);
#pragma unroll
    for (int ii = 0; ii < 8; ii++) {
        int row = m0 + ty * 8 + ii;
        float4 v;
        v.x = fmaxf(acc[ii][0] + bias4.x, 0.f);
        v.y = fmaxf(acc[ii][1] + bias4.y, 0.f);
        v.z = fmaxf(acc[ii][2] + bias4.z, 0.f);
        v.w = fmaxf(acc[ii][3] + bias4.w, 0.f);
        *(float4*)(C + (size_t)row * N + n0 + tx * 4) = v;
    }
}

// ===========================================================================
// Stage 1 SIMT GEMM: OW = H1o @ Wf + bf ;  D = H1d @ W2d + b2d  (N=128, K=256)
// Epilogue emits bf16 hi/lo split for the tensor-core scores kernel.
// ===========================================================================
__global__ __launch_bounds__(256)
void gemm_stage1_kernel(const float* __restrict__ W2d, const float* __restrict__ b2d)
{
    const int K = HH, N = HD2;
    const int z = blockIdx.z;
    const float* A    = z ? g_H1d : g_H1o;
    const float* Bm   = z ? W2d   : g_Wf;
    const float* bias = z ? b2d   : g_bf;
    __nv_bfloat16* Chi = z ? g_Dhi : g_OWhi;
    __nv_bfloat16* Clo = z ? g_Dlo : g_OWlo;

    __shared__ float As[16][132];
    __shared__ float Bs[16][64];

    const int tid = threadIdx.x;
    const int tx  = tid & 15;
    const int ty  = tid >> 4;
    const int m0  = blockIdx.y * 128;
    const int n0  = blockIdx.x * 64;
    const int ar  = tid >> 2;
    const int ac  = (tid & 3) << 2;
    const int br  = tid >> 4;
    const int bc  = (tid & 15) << 2;

    const float* Ap0 = A + (size_t)(m0 + ar) * K;
    const float* Ap1 = A + (size_t)(m0 + ar + 64) * K;

    float acc[8][4];
#pragma unroll
    for (int i = 0; i < 8; i++)
#pragma unroll
        for (int j = 0; j < 4; j++) acc[i][j] = 0.f;

    for (int k0 = 0; k0 < K; k0 += 16) {
        float4 a0v = *(const float4*)(Ap0 + k0 + ac);
        float4 a1v = *(const float4*)(Ap1 + k0 + ac);
        float4 bv  = *(const float4*)(Bm + (size_t)(k0 + br) * N + n0 + bc);
        __syncthreads();
        As[ac + 0][ar] = a0v.x; As[ac + 1][ar] = a0v.y;
        As[ac + 2][ar] = a0v.z; As[ac + 3][ar] = a0v.w;
        As[ac + 0][ar + 64] = a1v.x; As[ac + 1][ar + 64] = a1v.y;
        As[ac + 2][ar + 64] = a1v.z; As[ac + 3][ar + 64] = a1v.w;
        *(float4*)&Bs[br][bc] = bv;
        __syncthreads();
#pragma unroll
        for (int k = 0; k < 16; k++) {
            float4 aA = *(const float4*)&As[k][ty * 8];
            float4 aB = *(const float4*)&As[k][ty * 8 + 4];
            float4 b4 = *(const float4*)&Bs[k][tx * 4];
            float av[8] = {aA.x, aA.y, aA.z, aA.w, aB.x, aB.y, aB.z, aB.w};
            float bw[4] = {b4.x, b4.y, b4.z, b4.w};
#pragma unroll
            for (int i = 0; i < 8; i++)
#pragma unroll
                for (int j = 0; j < 4; j++)
                    acc[i][j] = fmaf(av[i], bw[j], acc[i][j]);
        }
    }

    float4 bias4 = *(const float4*)(bias + n0 + tx * 4);
    uint2* hi2 = (uint2*)Chi;
    uint2* lo2 = (uint2*)Clo;
#pragma unroll
    for (int ii = 0; ii < 8; ii++) {
        int row = m0 + ty * 8 + ii;
        float4 v;
        v.x = acc[ii][0] + bias4.x;
        v.y = acc[ii][1] + bias4.y;
        v.z = acc[ii][2] + bias4.z;
        v.w = acc[ii][3] + bias4.w;
        // bf16 hi/lo split: v = hi + lo + O(2^-18 * v)
        float hx = __bfloat162float(__float2bfloat16(v.x));
        float hy = __bfloat162float(__float2bfloat16(v.y));
        float hz = __bfloat162float(__float2bfloat16(v.z));
        float hw = __bfloat162float(__float2bfloat16(v.w));
        uint2 h, l;
        h.x = pack_bf2(v.x, v.y);
        h.y = pack_bf2(v.z, v.w);
        l.x = pack_bf2(v.x - hx, v.y - hy);
        l.y = pack_bf2(v.z - hz, v.w - hw);
        size_t idx = ((size_t)row * N + n0 + tx * 4) >> 2;
        hi2[idx] = h;
        lo2[idx] = l;
    }
}

// ===========================================================================
// Tensor-core (mma.sync) scores + horizon expansion.
//   S[b,i,j] = sum_l OW[b,i,l]*D[b,j,l] + bb    (3-pass bf16 split)
//   out[b,t,i,j] = relu(S*wh[t] + bh[t])
// One CTA per 128(i) x 256(j) tile, K=128 resident in SMEM.
// 8 warps = 2(M) x 4(N), warp tile 64x64, mma.sync.m16n8k16 bf16.
// SMEM rows = 128 bf16 = 16 x 16B granules, swizzle g ^= (row & 7):
//   conflict-free for both the float4 stores and every ldmatrix phase.
// Epilogue stages the fp32 scores tile (pitch 264 floats) then does fully
// coalesced 512B-per-warp STG.128 with the 12-horizon expansion.
// ===========================================================================
#define SMA_HI   0
#define SMA_LO   32768
#define SMB_HI   65536
#define SMB_LO   131072
#define SM_TOTAL 196608    // 192 KB dynamic smem

__global__ __launch_bounds__(256)
void scores_mma_kernel(const float* __restrict__ bbp,
                       const float* __restrict__ whp,
                       const float* __restrict__ bhp,
                       float* __restrict__ out)
{
    extern __shared__ __align__(1024) char smem[];
    const int tid  = threadIdx.x;
    const int lane = tid & 31;
    const int wid  = tid >> 5;
    const int b  = blockIdx.z;
    const int i0 = blockIdx.y * 128;
    const int j0 = blockIdx.x * 256;

    // ---- global -> swizzled SMEM (coalesced 16B chunks) ----
    const uint4* a_hi = (const uint4*)(g_OWhi + (size_t)(b * NN + i0) * HD2);
    const uint4* a_lo = (const uint4*)(g_OWlo + (size_t)(b * NN + i0) * HD2);
    const uint4* b_hi = (const uint4*)(g_Dhi  + (size_t)(b * NN + j0) * HD2);
    const uint4* b_lo = (const uint4*)(g_Dlo  + (size_t)(b * NN + j0) * HD2);

#pragma unroll
    for (int half = 0; half < 2; half++) {
        const uint4* asrc = half ? a_lo : a_hi;
        char* adst = smem + (half ? SMA_LO : SMA_HI);
#pragma unroll
        for (int it = 0; it < 8; it++) {       // A: 128 rows x 16 granules
            int idx = it * 256 + tid;
            int r = idx >> 4, g = idx & 15;
            *(uint4*)(adst + r * 256 + ((g ^ (r & 7)) << 4)) = asrc[idx];
        }
        const uint4* bsrc = half ? b_lo : b_hi;
        char* bdst = smem + (half ? SMB_LO : SMB_HI);
#pragma unroll
        for (int it = 0; it < 16; it++) {      // B: 256 rows x 16 granules
            int idx = it * 256 + tid;
            int r = idx >> 4, g = idx & 15;
            *(uint4*)(bdst + r * 256 + ((g ^ (r & 7)) << 4)) = bsrc[idx];
        }
    }
    __syncthreads();

    const uint32_t sbase = smem_u32(smem);
    const int wm = wid & 1;        // M half (64 rows)
    const int wn = wid >> 1;       // N quarter (64 cols)

    float acc[4][8][4];
#pragma unroll
    for (int mt = 0; mt < 4; mt++)
#pragma unroll
        for (int nt = 0; nt < 8; nt++)
#pragma unroll
            for (int e = 0; e < 4; e++) acc[mt][nt][e] = 0.f;

    // ldmatrix lane address components (non-trans for both operands:
    // A row-major [m,k], B = D[j,k] row-major == col-major B for row.col mma)
    const int a_rlane = (lane & 15);          // + wm*64 + mt*16
    const int a_gsel  = (lane >> 4);          // 0/1 -> k granule
    const int b_rlane = (lane & 7) + ((lane >> 4) << 3);  // + wn*64 + p*16
    const int b_gsel  = (lane >> 3) & 1;

#pragma unroll
    for (int pass = 0; pass < 3; pass++) {    // hi*hi, hi*lo, lo*hi
        const uint32_t Abase = sbase + ((pass == 2) ? SMA_LO : SMA_HI);
        const uint32_t Bbase = sbase + ((pass == 1) ? SMB_LO : SMB_HI);
#pragma unroll
        for (int kc = 0; kc < 8; kc++) {      // K = 8 x 16
            uint32_t bf[16];
#pragma unroll
            for (int p = 0; p < 4; p++) {     // 4 x ldmatrix.x4 -> 8 n-tiles
                int r = wn * 64 + p * 16 + b_rlane;
                int g = 2 * kc + b_gsel;
                ldsm_x4(&bf[p * 4], Bbase + r * 256 + ((g ^ (r & 7)) << 4));
            }
#pragma unroll
            for (int mt = 0; mt < 4; mt++) {
                int r = wm * 64 + mt * 16 + a_rlane;
                int g = 2 * kc + a_gsel;
                uint32_t af[4];
                ldsm_x4(af, Abase + r * 256 + ((g ^ (r & 7)) << 4));
#pragma unroll
                for (int nt = 0; nt < 8; nt++)
                    mma16816(acc[mt][nt], af, &bf[nt * 2]);
            }
        }
    }

    // ---- stage scores tile to SMEM (fp32, pitch 264 floats) ----
    __syncthreads();   // all ldmatrix reads done; smem reusable
    float* stage = (float*)smem;
    const int qr = lane >> 2;
    const int qc = lane & 3;
#pragma unroll
    for (int mt = 0; mt < 4; mt++)
#pragma unroll
        for (int nt = 0; nt < 8; nt++) {
            int row = wm * 64 + mt * 16 + qr;
            int cf  = wn * 64 + nt * 8 + qc * 2;
            *(float2*)&stage[row * 264 + cf] =
                make_float2(acc[mt][nt][0], acc[mt][nt][1]);
            *(float2*)&stage[(row + 8) * 264 + cf] =
                make_float2(acc[mt][nt][2], acc[mt][nt][3]);
        }
    __syncthreads();

    // ---- coalesced expansion: out[b,t,i,j] = relu(S*wh[t] + (bb*wh[t]+bh[t]))
    const float bbv = *bbp;
    float w[TT], ht[TT];
#pragma unroll
    for (int t = 0; t < TT; t++) {
        w[t]  = whp[t];
        ht[t] = fmaf(bbv, w[t], bhp[t]);
    }

#pragma unroll 1
    for (int it = 0; it < 32; it++) {
        int idx = it * 256 + tid;
        int row = idx >> 6;                   // 0..127
        int c4  = idx & 63;                   // float4 column
        float4 s = *(const float4*)&stage[row * 264 + c4 * 4];
        size_t off0 = ((size_t)(b * TT) * NN + (size_t)(i0 + row)) * NN
                    + (size_t)(j0 + c4 * 4);
#pragma unroll
        for (int t = 0; t < TT; t++) {
            float4 v;
            v.x = fmaxf(fmaf(s.x, w[t], ht[t]), 0.f);
            v.y = fmaxf(fmaf(s.y, w[t], ht[t]), 0.f);
            v.z = fmaxf(fmaf(s.z, w[t], ht[t]), 0.f);
            v.w = fmaxf(fmaf(s.w, w[t], ht[t]), 0.f);
            *(float4*)(out + off0 + (size_t)t * NN * NN) = v;
        }
    }
}

// ===========================================================================
extern "C" void kernel_launch(void* const* d_in, const int* in_sizes, int n_in,
                              void* d_out, int out_size)
{
    const float* X   = (const float*)d_in[0];
    const float* W1o = (const float*)d_in[1];
    const float* b1o = (const float*)d_in[2];
    const float* W2o = (const float*)d_in[3];
    const float* b2o = (const float*)d_in[4];
    const float* W1d = (const float*)d_in[5];
    const float* b1d = (const float*)d_in[6];
    const float* W2d = (const float*)d_in[7];
    const float* b2d = (const float*)d_in[8];
    const float* Wb  = (const float*)d_in[9];
    const float* bb  = (const float*)d_in[10];
    const float* wh  = (const float*)d_in[11];
    const float* bh  = (const float*)d_in[12];
    float* out = (float*)d_out;

    static bool attr_set = false;
    if (!attr_set) {
        cudaFuncSetAttribute(scores_mma_kernel,
                             cudaFuncAttributeMaxDynamicSharedMemorySize, SM_TOTAL);
        attr_set = true;
    }

    // Fold Wb into the o-path second layer
    fuse_w_kernel<<<HH, HD2>>>(W2o, b2o, Wb);

    // Stage 0: H1o/H1d = relu(X @ W1{o,d} + b1{o,d})
    gemm_stage0_kernel<<<dim3(HH / 64, MTOT / 128, 2), 256>>>(X, W1o, W1d, b1o, b1d);

    // Stage 1: OW/D (emitted as bf16 hi/lo splits)
    gemm_stage1_kernel<<<dim3(HD2 / 64, MTOT / 128, 2), 256>>>(W2d, b2d);

    // Tensor-core scores GEMM + horizon expansion -> (B,T,N,N)
    scores_mma_kernel<<<dim3(NN / 256, NN / 128, NB), 256, SM_TOTAL>>>(bb, wh, bh, out);
}

// round 12
// speedup vs baseline: 1.0403x; 1.0403x over previous
#include <cuda_runtime.h>
#include <cuda_bf16.h>
#include <stdint.h>

// Shapes (fixed by the problem)
#define NB   4
#define NN   1024
#define HH   256
#define HD2  128
#define TT   12
#define MTOT (NB * NN)   // 4096

// Scratch (static device allocations are allowed)
__device__ __align__(256) float g_H1o[MTOT * HH];   // relu(X@W1o+b1o)
__device__ __align__(256) float g_H1d[MTOT * HH];   // relu(X@W1d+b1d)
__device__ __align__(256) float g_Wf [HH * HD2];    // W2o @ Wb
__device__ __align__(256) float g_bf [HD2];         // b2o @ Wb
// bf16 hi/lo splits consumed by the tensor-core scores kernel
__device__ __align__(256) __nv_bfloat16 g_OWhi[MTOT * HD2];
__device__ __align__(256) __nv_bfloat16 g_OWlo[MTOT * HD2];
__device__ __align__(256) __nv_bfloat16 g_Dhi [MTOT * HD2];
__device__ __align__(256) __nv_bfloat16 g_Dlo [MTOT * HD2];

// ===========================================================================
// Warp-level tensor-core helpers (base ISA: compile clean at compute_103)
// ===========================================================================
__device__ __forceinline__ uint32_t smem_u32(const void* p) {
    uint32_t a;
    asm("{ .reg .u64 t; cvta.to.shared.u64 t, %1; cvt.u32.u64 %0, t; }"
        : "=r"(a) : "l"(p));
    return a;
}

__device__ __forceinline__ void ldsm_x4(uint32_t* r, uint32_t addr) {
    asm volatile("ldmatrix.sync.aligned.m8n8.x4.shared.b16 {%0,%1,%2,%3}, [%4];"
                 : "=r"(r[0]), "=r"(r[1]), "=r"(r[2]), "=r"(r[3]) : "r"(addr));
}

// D(16x8,f32) += A(16x16 row-major bf16) * B(16x8 col-major bf16)
__device__ __forceinline__ void mma16816(float* d, const uint32_t* a, const uint32_t* b) {
    asm volatile(
        "mma.sync.aligned.m16n8k16.row.col.f32.bf16.bf16.f32 "
        "{%0,%1,%2,%3}, {%4,%5,%6,%7}, {%8,%9}, {%0,%1,%2,%3};"
        : "+f"(d[0]), "+f"(d[1]), "+f"(d[2]), "+f"(d[3])
        : "r"(a[0]), "r"(a[1]), "r"(a[2]), "r"(a[3]), "r"(b[0]), "r"(b[1]));
}

__device__ __forceinline__ unsigned pack_bf2(float a, float b) {
    __nv_bfloat162 t = __floats2bfloat162_rn(a, b);
    return ((unsigned)__bfloat16_as_ushort(t.y) << 16) | (unsigned)__bfloat16_as_ushort(t.x);
}

// ===========================================================================
// Fold Wb into the second o-layer:  Wf = W2o @ Wb, bf = b2o @ Wb
// ===========================================================================
__global__ void fuse_w_kernel(const float* __restrict__ W2o,
                              const float* __restrict__ b2o,
                              const float* __restrict__ Wb)
{
    int n = threadIdx.x;   // 0..127
    int k = blockIdx.x;    // 0..255
    float s = 0.f;
#pragma unroll 8
    for (int l = 0; l < HD2; l++)
        s = fmaf(W2o[k * HD2 + l], Wb[l * HD2 + n], s);
    g_Wf[k * HD2 + n] = s;
    if (k == 0) {
        float s2 = 0.f;
#pragma unroll 8
        for (int l = 0; l < HD2; l++)
            s2 = fmaf(b2o[l], Wb[l * HD2 + n], s2);
        g_bf[n] = s2;
    }
}

// ===========================================================================
// Stage 0 SIMT GEMM: H1{o,d} = relu(X @ W1{o,d} + b1{o,d}), M=4096 N=256 K=256
// tiles 128x64x16, thread tile 8x4, 256 threads, z selects o/d
// ===========================================================================
__global__ __launch_bounds__(256)
void gemm_stage0_kernel(const float* __restrict__ X,
                        const float* __restrict__ W1o, const float* __restrict__ W1d,
                        const float* __restrict__ b1o, const float* __restrict__ b1d)
{
    const int K = HH, N = HH;
    const int z = blockIdx.z;
    const float* A    = X;
    const float* Bm   = z ? W1d : W1o;
    const float* bias = z ? b1d : b1o;
    float* C          = z ? g_H1d : g_H1o;

    __shared__ float As[16][132];
    __shared__ float Bs[16][64];

    const int tid = threadIdx.x;
    const int tx  = tid & 15;
    const int ty  = tid >> 4;
    const int m0  = blockIdx.y * 128;
    const int n0  = blockIdx.x * 64;
    const int ar  = tid >> 2;
    const int ac  = (tid & 3) << 2;
    const int br  = tid >> 4;
    const int bc  = (tid & 15) << 2;

    const float* Ap0 = A + (size_t)(m0 + ar) * K;
    const float* Ap1 = A + (size_t)(m0 + ar + 64) * K;

    float acc[8][4];
#pragma unroll
    for (int i = 0; i < 8; i++)
#pragma unroll
        for (int j = 0; j < 4; j++) acc[i][j] = 0.f;

    for (int k0 = 0; k0 < K; k0 += 16) {
        float4 a0v = *(const float4*)(Ap0 + k0 + ac);
        float4 a1v = *(const float4*)(Ap1 + k0 + ac);
        float4 bv  = *(const float4*)(Bm + (size_t)(k0 + br) * N + n0 + bc);
        __syncthreads();
        As[ac + 0][ar] = a0v.x; As[ac + 1][ar] = a0v.y;
        As[ac + 2][ar] = a0v.z; As[ac + 3][ar] = a0v.w;
        As[ac + 0][ar + 64] = a1v.x; As[ac + 1][ar + 64] = a1v.y;
        As[ac + 2][ar + 64] = a1v.z; As[ac + 3][ar + 64] = a1v.w;
        *(float4*)&Bs[br][bc] = bv;
        __syncthreads();
#pragma unroll
        for (int k = 0; k < 16; k++) {
            float4 aA = *(const float4*)&As[k][ty * 8];
            float4 aB = *(const float4*)&As[k][ty * 8 + 4];
            float4 b4 = *(const float4*)&Bs[k][tx * 4];
            float av[8] = {aA.x, aA.y, aA.z, aA.w, aB.x, aB.y, aB.z, aB.w};
            float bw[4] = {b4.x, b4.y, b4.z, b4.w};
#pragma unroll
            for (int i = 0; i < 8; i++)
#pragma unroll
                for (int j = 0; j < 4; j++)
                    acc[i][j] = fmaf(av[i], bw[j], acc[i][j]);
        }
    }

    float4 bias4 = *(const float4*)(bias + n0 + tx * 4);
#pragma unroll
    for (int ii = 0; ii < 8; ii++) {
        int row = m0 + ty * 8 + ii;
        float4 v;
        v.x = fmaxf(acc[ii][0] + bias4.x, 0.f);
        v.y = fmaxf(acc[ii][1] + bias4.y, 0.f);
        v.z = fmaxf(acc[ii][2] + bias4.z, 0.f);
        v.w = fmaxf(acc[ii][3] + bias4.w, 0.f);
        *(float4*)(C + (size_t)row * N + n0 + tx * 4) = v;
    }
}

// ===========================================================================
// Stage 1 SIMT GEMM: OW = H1o @ Wf + bf ;  D = H1d @ W2d + b2d  (N=128, K=256)
// Epilogue emits bf16 hi/lo split for the tensor-core scores kernel.
// ===========================================================================
__global__ __launch_bounds__(256)
void gemm_stage1_kernel(const float* __restrict__ W2d, const float* __restrict__ b2d)
{
    const int K = HH, N = HD2;
    const int z = blockIdx.z;
    const float* A    = z ? g_H1d : g_H1o;
    const float* Bm   = z ? W2d   : g_Wf;
    const float* bias = z ? b2d   : g_bf;
    __nv_bfloat16* Chi = z ? g_Dhi : g_OWhi;
    __nv_bfloat16* Clo = z ? g_Dlo : g_OWlo;

    __shared__ float As[16][132];
    __shared__ float Bs[16][64];

    const int tid = threadIdx.x;
    const int tx  = tid & 15;
    const int ty  = tid >> 4;
    const int m0  = blockIdx.y * 128;
    const int n0  = blockIdx.x * 64;
    const int ar  = tid >> 2;
    const int ac  = (tid & 3) << 2;
    const int br  = tid >> 4;
    const int bc  = (tid & 15) << 2;

    const float* Ap0 = A + (size_t)(m0 + ar) * K;
    const float* Ap1 = A + (size_t)(m0 + ar + 64) * K;

    float acc[8][4];
#pragma unroll
    for (int i = 0; i < 8; i++)
#pragma unroll
        for (int j = 0; j < 4; j++) acc[i][j] = 0.f;

    for (int k0 = 0; k0 < K; k0 += 16) {
        float4 a0v = *(const float4*)(Ap0 + k0 + ac);
        float4 a1v = *(const float4*)(Ap1 + k0 + ac);
        float4 bv  = *(const float4*)(Bm + (size_t)(k0 + br) * N + n0 + bc);
        __syncthreads();
        As[ac + 0][ar] = a0v.x; As[ac + 1][ar] = a0v.y;
        As[ac + 2][ar] = a0v.z; As[ac + 3][ar] = a0v.w;
        As[ac + 0][ar + 64] = a1v.x; As[ac + 1][ar + 64] = a1v.y;
        As[ac + 2][ar + 64] = a1v.z; As[ac + 3][ar + 64] = a1v.w;
        *(float4*)&Bs[br][bc] = bv;
        __syncthreads();
#pragma unroll
        for (int k = 0; k < 16; k++) {
            float4 aA = *(const float4*)&As[k][ty * 8];
            float4 aB = *(const float4*)&As[k][ty * 8 + 4];
            float4 b4 = *(const float4*)&Bs[k][tx * 4];
            float av[8] = {aA.x, aA.y, aA.z, aA.w, aB.x, aB.y, aB.z, aB.w};
            float bw[4] = {b4.x, b4.y, b4.z, b4.w};
#pragma unroll
            for (int i = 0; i < 8; i++)
#pragma unroll
                for (int j = 0; j < 4; j++)
                    acc[i][j] = fmaf(av[i], bw[j], acc[i][j]);
        }
    }

    float4 bias4 = *(const float4*)(bias + n0 + tx * 4);
    uint2* hi2 = (uint2*)Chi;
    uint2* lo2 = (uint2*)Clo;
#pragma unroll
    for (int ii = 0; ii < 8; ii++) {
        int row = m0 + ty * 8 + ii;
        float4 v;
        v.x = acc[ii][0] + bias4.x;
        v.y = acc[ii][1] + bias4.y;
        v.z = acc[ii][2] + bias4.z;
        v.w = acc[ii][3] + bias4.w;
        // bf16 hi/lo split: v = hi + lo + O(2^-18 * v)
        float hx = __bfloat162float(__float2bfloat16(v.x));
        float hy = __bfloat162float(__float2bfloat16(v.y));
        float hz = __bfloat162float(__float2bfloat16(v.z));
        float hw = __bfloat162float(__float2bfloat16(v.w));
        uint2 h, l;
        h.x = pack_bf2(v.x, v.y);
        h.y = pack_bf2(v.z, v.w);
        l.x = pack_bf2(v.x - hx, v.y - hy);
        l.y = pack_bf2(v.z - hz, v.w - hw);
        size_t idx = ((size_t)row * N + n0 + tx * 4) >> 2;
        hi2[idx] = h;
        lo2[idx] = l;
    }
}

// ===========================================================================
// Tensor-core (mma.sync) scores + horizon expansion.
//   S[b,i,j] = sum_l OW[b,i,l]*D[b,j,l] + bb    (3-pass bf16 split)
//   out[b,t,i,j] = relu(S*wh[t] + bh[t])
// One CTA per 128(i) x 256(j) tile, K=128 resident in SMEM.
// 8 warps = 2(M) x 4(N), warp tile 64x64, mma.sync.m16n8k16 bf16.
// SMEM rows = 128 bf16 = 16 x 16B granules, swizzle g ^= (row & 7):
//   conflict-free for both the float4 stores and every ldmatrix phase.
// Epilogue stages the fp32 scores tile (pitch 264 floats) then does fully
// coalesced 512B-per-warp STG.128 with the 12-horizon expansion.
// ===========================================================================
#define SMA_HI   0
#define SMA_LO   32768
#define SMB_HI   65536
#define SMB_LO   131072
#define SM_TOTAL 196608    // 192 KB dynamic smem

__global__ __launch_bounds__(256)
void scores_mma_kernel(const float* __restrict__ bbp,
                       const float* __restrict__ whp,
                       const float* __restrict__ bhp,
                       float* __restrict__ out)
{
    extern __shared__ __align__(1024) char smem[];
    const int tid  = threadIdx.x;
    const int lane = tid & 31;
    const int wid  = tid >> 5;
    const int b  = blockIdx.z;
    const int i0 = blockIdx.y * 128;
    const int j0 = blockIdx.x * 256;

    // ---- global -> swizzled SMEM (coalesced 16B chunks) ----
    const uint4* a_hi = (const uint4*)(g_OWhi + (size_t)(b * NN + i0) * HD2);
    const uint4* a_lo = (const uint4*)(g_OWlo + (size_t)(b * NN + i0) * HD2);
    const uint4* b_hi = (const uint4*)(g_Dhi  + (size_t)(b * NN + j0) * HD2);
    const uint4* b_lo = (const uint4*)(g_Dlo  + (size_t)(b * NN + j0) * HD2);

#pragma unroll
    for (int half = 0; half < 2; half++) {
        const uint4* asrc = half ? a_lo : a_hi;
        char* adst = smem + (half ? SMA_LO : SMA_HI);
#pragma unroll
        for (int it = 0; it < 8; it++) {       // A: 128 rows x 16 granules
            int idx = it * 256 + tid;
            int r = idx >> 4, g = idx & 15;
            *(uint4*)(adst + r * 256 + ((g ^ (r & 7)) << 4)) = asrc[idx];
        }
        const uint4* bsrc = half ? b_lo : b_hi;
        char* bdst = smem + (half ? SMB_LO : SMB_HI);
#pragma unroll
        for (int it = 0; it < 16; it++) {      // B: 256 rows x 16 granules
            int idx = it * 256 + tid;
            int r = idx >> 4, g = idx & 15;
            *(uint4*)(bdst + r * 256 + ((g ^ (r & 7)) << 4)) = bsrc[idx];
        }
    }
    __syncthreads();

    const uint32_t sbase = smem_u32(smem);
    const int wm = wid & 1;        // M half (64 rows)
    const int wn = wid >> 1;       // N quarter (64 cols)

    float acc[4][8][4];
#pragma unroll
    for (int mt = 0; mt < 4; mt++)
#pragma unroll
        for (int nt = 0; nt < 8; nt++)
#pragma unroll
            for (int e = 0; e < 4; e++) acc[mt][nt][e] = 0.f;

    // ldmatrix lane address components (non-trans for both operands:
    // A row-major [m,k], B = D[j,k] row-major == col-major B for row.col mma)
    const int a_rlane = (lane & 15);          // + wm*64 + mt*16
    const int a_gsel  = (lane >> 4);          // 0/1 -> k granule
    const int b_rlane = (lane & 7) + ((lane >> 4) << 3);  // + wn*64 + p*16
    const int b_gsel  = (lane >> 3) & 1;

#pragma unroll
    for (int pass = 0; pass < 3; pass++) {    // hi*hi, hi*lo, lo*hi
        const uint32_t Abase = sbase + ((pass == 2) ? SMA_LO : SMA_HI);
        const uint32_t Bbase = sbase + ((pass == 1) ? SMB_LO : SMB_HI);
#pragma unroll
        for (int kc = 0; kc < 8; kc++) {      // K = 8 x 16
            uint32_t bf[16];
#pragma unroll
            for (int p = 0; p < 4; p++) {     // 4 x ldmatrix.x4 -> 8 n-tiles
                int r = wn * 64 + p * 16 + b_rlane;
                int g = 2 * kc + b_gsel;
                ldsm_x4(&bf[p * 4], Bbase + r * 256 + ((g ^ (r & 7)) << 4));
            }
#pragma unroll
            for (int mt = 0; mt < 4; mt++) {
                int r = wm * 64 + mt * 16 + a_rlane;
                int g = 2 * kc + a_gsel;
                uint32_t af[4];
                ldsm_x4(af, Abase + r * 256 + ((g ^ (r & 7)) << 4));
#pragma unroll
                for (int nt = 0; nt < 8; nt++)
                    mma16816(acc[mt][nt], af, &bf[nt * 2]);
            }
        }
    }

    // ---- stage scores tile to SMEM (fp32, pitch 264 floats) ----
    __syncthreads();   // all ldmatrix reads done; smem reusable
    float* stage = (float*)smem;
    const int qr = lane >> 2;
    const int qc = lane & 3;
#pragma unroll
    for (int mt = 0; mt < 4; mt++)
#pragma unroll
        for (int nt = 0; nt < 8; nt++) {
            int row = wm * 64 + mt * 16 + qr;
            int cf  = wn * 64 + nt * 8 + qc * 2;
            *(float2*)&stage[row * 264 + cf] =
                make_float2(acc[mt][nt][0], acc[mt][nt][1]);
            *(float2*)&stage[(row + 8) * 264 + cf] =
                make_float2(acc[mt][nt][2], acc[mt][nt][3]);
        }
    __syncthreads();

    // ---- coalesced expansion: out[b,t,i,j] = relu(S*wh[t] + (bb*wh[t]+bh[t]))
    const float bbv = *bbp;
    float w[TT], ht[TT];
#pragma unroll
    for (int t = 0; t < TT; t++) {
        w[t]  = whp[t];
        ht[t] = fmaf(bbv, w[t], bhp[t]);
    }

#pragma unroll 1
    for (int it = 0; it < 32; it++) {
        int idx = it * 256 + tid;
        int row = idx >> 6;                   // 0..127
        int c4  = idx & 63;                   // float4 column
        float4 s = *(const float4*)&stage[row * 264 + c4 * 4];
        size_t off0 = ((size_t)(b * TT) * NN + (size_t)(i0 + row)) * NN
                    + (size_t)(j0 + c4 * 4);
#pragma unroll
        for (int t = 0; t < TT; t++) {
            float4 v;
            v.x = fmaxf(fmaf(s.x, w[t], ht[t]), 0.f);
            v.y = fmaxf(fmaf(s.y, w[t], ht[t]), 0.f);
            v.z = fmaxf(fmaf(s.z, w[t], ht[t]), 0.f);
            v.w = fmaxf(fmaf(s.w, w[t], ht[t]), 0.f);
            *(float4*)(out + off0 + (size_t)t * NN * NN) = v;
        }
    }
}

// ===========================================================================
extern "C" void kernel_launch(void* const* d_in, const int* in_sizes, int n_in,
                              void* d_out, int out_size)
{
    const float* X   = (const float*)d_in[0];
    const float* W1o = (const float*)d_in[1];
    const float* b1o = (const float*)d_in[2];
    const float* W2o = (const float*)d_in[3];
    const float* b2o = (const float*)d_in[4];
    const float* W1d = (const float*)d_in[5];
    const float* b1d = (const float*)d_in[6];
    const float* W2d = (const float*)d_in[7];
    const float* b2d = (const float*)d_in[8];
    const float* Wb  = (const float*)d_in[9];
    const float* bb  = (const float*)d_in[10];
    const float* wh  = (const float*)d_in[11];
    const float* bh  = (const float*)d_in[12];
    float* out = (float*)d_out;

    static bool attr_set = false;
    if (!attr_set) {
        cudaFuncSetAttribute(scores_mma_kernel,
                             cudaFuncAttributeMaxDynamicSharedMemorySize, SM_TOTAL);
        attr_set = true;
    }

    // Fold Wb into the o-path second layer
    fuse_w_kernel<<<HH, HD2>>>(W2o, b2o, Wb);

    // Stage 0: H1o/H1d = relu(X @ W1{o,d} + b1{o,d})
    gemm_stage0_kernel<<<dim3(HH / 64, MTOT / 128, 2), 256>>>(X, W1o, W1d, b1o, b1d);

    // Stage 1: OW/D (emitted as bf16 hi/lo splits)
    gemm_stage1_kernel<<<dim3(HD2 / 64, MTOT / 128, 2), 256>>>(W2d, b2d);

    // Tensor-core scores GEMM + horizon expansion -> (B,T,N,N)
    scores_mma_kernel<<<dim3(NN / 256, NN / 128, NB), 256, SM_TOTAL>>>(bb, wh, bh, out);
}

// round 13
// speedup vs baseline: 1.0496x; 1.0089x over previous
#include <cuda_runtime.h>
#include <cuda_bf16.h>
#include <stdint.h>

// Shapes (fixed by the problem)
#define NB   4
#define NN   1024
#define HH   256
#define HD2  128
#define TT   12
#define MTOT (NB * NN)   // 4096

// Scratch (static device allocations are allowed)
__device__ __align__(256) float g_H1o[MTOT * HH];   // relu(X@W1o+b1o)
__device__ __align__(256) float g_H1d[MTOT * HH];   // relu(X@W1d+b1d)
__device__ __align__(256) float g_Wf [HH * HD2];    // W2o @ Wb
__device__ __align__(256) float g_bf [HD2];         // b2o @ Wb
// bf16 hi/lo splits consumed by the tensor-core scores kernel
__device__ __align__(256) __nv_bfloat16 g_OWhi[MTOT * HD2];
__device__ __align__(256) __nv_bfloat16 g_OWlo[MTOT * HD2];
__device__ __align__(256) __nv_bfloat16 g_Dhi [MTOT * HD2];
__device__ __align__(256) __nv_bfloat16 g_Dlo [MTOT * HD2];

// ===========================================================================
// Warp-level tensor-core helpers (base ISA: compile clean at compute_103)
// ===========================================================================
__device__ __forceinline__ uint32_t smem_u32(const void* p) {
    uint32_t a;
    asm("{ .reg .u64 t; cvta.to.shared.u64 t, %1; cvt.u32.u64 %0, t; }"
        : "=r"(a) : "l"(p));
    return a;
}

__device__ __forceinline__ void ldsm_x4(uint32_t* r, uint32_t addr) {
    asm volatile("ldmatrix.sync.aligned.m8n8.x4.shared.b16 {%0,%1,%2,%3}, [%4];"
                 : "=r"(r[0]), "=r"(r[1]), "=r"(r[2]), "=r"(r[3]) : "r"(addr));
}

// D(16x8,f32) += A(16x16 row-major bf16) * B(16x8 col-major bf16)
__device__ __forceinline__ void mma16816(float* d, const uint32_t* a, const uint32_t* b) {
    asm volatile(
        "mma.sync.aligned.m16n8k16.row.col.f32.bf16.bf16.f32 "
        "{%0,%1,%2,%3}, {%4,%5,%6,%7}, {%8,%9}, {%0,%1,%2,%3};"
        : "+f"(d[0]), "+f"(d[1]), "+f"(d[2]), "+f"(d[3])
        : "r"(a[0]), "r"(a[1]), "r"(a[2]), "r"(a[3]), "r"(b[0]), "r"(b[1]));
}

__device__ __forceinline__ unsigned pack_bf2(float a, float b) {
    __nv_bfloat162 t = __floats2bfloat162_rn(a, b);
    return ((unsigned)__bfloat16_as_ushort(t.y) << 16) | (unsigned)__bfloat16_as_ushort(t.x);
}

// ===========================================================================
// Fold Wb into the second o-layer:  Wf = W2o @ Wb, bf = b2o @ Wb
// ===========================================================================
__global__ void fuse_w_kernel(const float* __restrict__ W2o,
                              const float* __restrict__ b2o,
                              const float* __restrict__ Wb)
{
    int n = threadIdx.x;   // 0..127
    int k = blockIdx.x;    // 0..255
    float s = 0.f;
#pragma unroll 8
    for (int l = 0; l < HD2; l++)
        s = fmaf(W2o[k * HD2 + l], Wb[l * HD2 + n], s);
    g_Wf[k * HD2 + n] = s;
    if (k == 0) {
        float s2 = 0.f;
#pragma unroll 8
        for (int l = 0; l < HD2; l++)
            s2 = fmaf(b2o[l], Wb[l * HD2 + n], s2);
        g_bf[n] = s2;
    }
}

// ===========================================================================
// Stage 0 SIMT GEMM: H1{o,d} = relu(X @ W1{o,d} + b1{o,d}), M=4096 N=256 K=256
// tiles 128x64x16, thread tile 8x4, 256 threads, z selects o/d
// ===========================================================================
__global__ __launch_bounds__(256)
void gemm_stage0_kernel(const float* __restrict__ X,
                        const float* __restrict__ W1o, const float* __restrict__ W1d,
                        const float* __restrict__ b1o, const float* __restrict__ b1d)
{
    const int K = HH, N = HH;
    const int z = blockIdx.z;
    const float* A    = X;
    const float* Bm   = z ? W1d : W1o;
    const float* bias = z ? b1d : b1o;
    float* C          = z ? g_H1d : g_H1o;

    __shared__ float As[16][132];
    __shared__ float Bs[16][64];

    const int tid = threadIdx.x;
    const int tx  = tid & 15;
    const int ty  = tid >> 4;
    const int m0  = blockIdx.y * 128;
    const int n0  = blockIdx.x * 64;
    const int ar  = tid >> 2;
    const int ac  = (tid & 3) << 2;
    const int br  = tid >> 4;
    const int bc  = (tid & 15) << 2;

    const float* Ap0 = A + (size_t)(m0 + ar) * K;
    const float* Ap1 = A + (size_t)(m0 + ar + 64) * K;

    float acc[8][4];
#pragma unroll
    for (int i = 0; i < 8; i++)
#pragma unroll
        for (int j = 0; j < 4; j++) acc[i][j] = 0.f;

    for (int k0 = 0; k0 < K; k0 += 16) {
        float4 a0v = *(const float4*)(Ap0 + k0 + ac);
        float4 a1v = *(const float4*)(Ap1 + k0 + ac);
        float4 bv  = *(const float4*)(Bm + (size_t)(k0 + br) * N + n0 + bc);
        __syncthreads();
        As[ac + 0][ar] = a0v.x; As[ac + 1][ar] = a0v.y;
        As[ac + 2][ar] = a0v.z; As[ac + 3][ar] = a0v.w;
        As[ac + 0][ar + 64] = a1v.x; As[ac + 1][ar + 64] = a1v.y;
        As[ac + 2][ar + 64] = a1v.z; As[ac + 3][ar + 64] = a1v.w;
        *(float4*)&Bs[br][bc] = bv;
        __syncthreads();
#pragma unroll
        for (int k = 0; k < 16; k++) {
            float4 aA = *(const float4*)&As[k][ty * 8];
            float4 aB = *(const float4*)&As[k][ty * 8 + 4];
            float4 b4 = *(const float4*)&Bs[k][tx * 4];
            float av[8] = {aA.x, aA.y, aA.z, aA.w, aB.x, aB.y, aB.z, aB.w};
            float bw[4] = {b4.x, b4.y, b4.z, b4.w};
#pragma unroll
            for (int i = 0; i < 8; i++)
#pragma unroll
                for (int j = 0; j < 4; j++)
                    acc[i][j] = fmaf(av[i], bw[j], acc[i][j]);
        }
    }

    float4 bias4 = *(const float4*)(bias + n0 + tx * 4);
#pragma unroll
    for (int ii = 0; ii < 8; ii++) {
        int row = m0 + ty * 8 + ii;
        float4 v;
        v.x = fmaxf(acc[ii][0] + bias4.x, 0.f);
        v.y = fmaxf(acc[ii][1] + bias4.y, 0.f);
        v.z = fmaxf(acc[ii][2] + bias4.z, 0.f);
        v.w = fmaxf(acc[ii][3] + bias4.w, 0.f);
        *(float4*)(C + (size_t)row * N + n0 + tx * 4) = v;
    }
}

// ===========================================================================
// Stage 1 SIMT GEMM: OW = H1o @ Wf + bf ;  D = H1d @ W2d + b2d  (N=128, K=256)
// Epilogue emits bf16 hi/lo split for the tensor-core scores kernel.
// ===========================================================================
__global__ __launch_bounds__(256)
void gemm_stage1_kernel(const float* __restrict__ W2d, const float* __restrict__ b2d)
{
    const int K = HH, N = HD2;
    const int z = blockIdx.z;
    const float* A    = z ? g_H1d : g_H1o;
    const float* Bm   = z ? W2d   : g_Wf;
    const float* bias = z ? b2d   : g_bf;
    __nv_bfloat16* Chi = z ? g_Dhi : g_OWhi;
    __nv_bfloat16* Clo = z ? g_Dlo : g_OWlo;

    __shared__ float As[16][132];
    __shared__ float Bs[16][64];

    const int tid = threadIdx.x;
    const int tx  = tid & 15;
    const int ty  = tid >> 4;
    const int m0  = blockIdx.y * 128;
    const int n0  = blockIdx.x * 64;
    const int ar  = tid >> 2;
    const int ac  = (tid & 3) << 2;
    const int br  = tid >> 4;
    const int bc  = (tid & 15) << 2;

    const float* Ap0 = A + (size_t)(m0 + ar) * K;
    const float* Ap1 = A + (size_t)(m0 + ar + 64) * K;

    float acc[8][4];
#pragma unroll
    for (int i = 0; i < 8; i++)
#pragma unroll
        for (int j = 0; j < 4; j++) acc[i][j] = 0.f;

    for (int k0 = 0; k0 < K; k0 += 16) {
        float4 a0v = *(const float4*)(Ap0 + k0 + ac);
        float4 a1v = *(const float4*)(Ap1 + k0 + ac);
        float4 bv  = *(const float4*)(Bm + (size_t)(k0 + br) * N + n0 + bc);
        __syncthreads();
        As[ac + 0][ar] = a0v.x; As[ac + 1][ar] = a0v.y;
        As[ac + 2][ar] = a0v.z; As[ac + 3][ar] = a0v.w;
        As[ac + 0][ar + 64] = a1v.x; As[ac + 1][ar + 64] = a1v.y;
        As[ac + 2][ar + 64] = a1v.z; As[ac + 3][ar + 64] = a1v.w;
        *(float4*)&Bs[br][bc] = bv;
        __syncthreads();
#pragma unroll
        for (int k = 0; k < 16; k++) {
            float4 aA = *(const float4*)&As[k][ty * 8];
            float4 aB = *(const float4*)&As[k][ty * 8 + 4];
            float4 b4 = *(const float4*)&Bs[k][tx * 4];
            float av[8] = {aA.x, aA.y, aA.z, aA.w, aB.x, aB.y, aB.z, aB.w};
            float bw[4] = {b4.x, b4.y, b4.z, b4.w};
#pragma unroll
            for (int i = 0; i < 8; i++)
#pragma unroll
                for (int j = 0; j < 4; j++)
                    acc[i][j] = fmaf(av[i], bw[j], acc[i][j]);
        }
    }

    float4 bias4 = *(const float4*)(bias + n0 + tx * 4);
    uint2* hi2 = (uint2*)Chi;
    uint2* lo2 = (uint2*)Clo;
#pragma unroll
    for (int ii = 0; ii < 8; ii++) {
        int row = m0 + ty * 8 + ii;
        float4 v;
        v.x = acc[ii][0] + bias4.x;
        v.y = acc[ii][1] + bias4.y;
        v.z = acc[ii][2] + bias4.z;
        v.w = acc[ii][3] + bias4.w;
        // bf16 hi/lo split: v = hi + lo + O(2^-18 * v)
        float hx = __bfloat162float(__float2bfloat16(v.x));
        float hy = __bfloat162float(__float2bfloat16(v.y));
        float hz = __bfloat162float(__float2bfloat16(v.z));
        float hw = __bfloat162float(__float2bfloat16(v.w));
        uint2 h, l;
        h.x = pack_bf2(v.x, v.y);
        h.y = pack_bf2(v.z, v.w);
        l.x = pack_bf2(v.x - hx, v.y - hy);
        l.y = pack_bf2(v.z - hz, v.w - hw);
        size_t idx = ((size_t)row * N + n0 + tx * 4) >> 2;
        hi2[idx] = h;
        lo2[idx] = l;
    }
}

// ===========================================================================
// Tensor-core (mma.sync) scores + horizon expansion.
//   S[b,i,j] = sum_l OW[b,i,l]*D[b,j,l] + bb    (3-pass bf16 split)
//   out[b,t,i,j] = relu(S*wh[t] + bh[t])
// One CTA per 128(i) x 256(j) tile, K=128 resident in SMEM.
// 8 warps = 2(M) x 4(N), warp tile 64x64, mma.sync.m16n8k16 bf16.
// SMEM rows = 128 bf16 = 16 x 16B granules, swizzle g ^= (row & 7):
//   conflict-free for both the float4 stores and every ldmatrix phase.
// Epilogue stages the fp32 scores tile (pitch 264 floats) then does fully
// coalesced 512B-per-warp STG.128 with the 12-horizon expansion.
// ===========================================================================
#define SMA_HI   0
#define SMA_LO   32768
#define SMB_HI   65536
#define SMB_LO   131072
#define SM_TOTAL 196608    // 192 KB dynamic smem

__global__ __launch_bounds__(256)
void scores_mma_kernel(const float* __restrict__ bbp,
                       const float* __restrict__ whp,
                       const float* __restrict__ bhp,
                       float* __restrict__ out)
{
    extern __shared__ __align__(1024) char smem[];
    const int tid  = threadIdx.x;
    const int lane = tid & 31;
    const int wid  = tid >> 5;
    const int b  = blockIdx.z;
    const int i0 = blockIdx.y * 128;
    const int j0 = blockIdx.x * 256;

    // ---- global -> swizzled SMEM (coalesced 16B chunks) ----
    const uint4* a_hi = (const uint4*)(g_OWhi + (size_t)(b * NN + i0) * HD2);
    const uint4* a_lo = (const uint4*)(g_OWlo + (size_t)(b * NN + i0) * HD2);
    const uint4* b_hi = (const uint4*)(g_Dhi  + (size_t)(b * NN + j0) * HD2);
    const uint4* b_lo = (const uint4*)(g_Dlo  + (size_t)(b * NN + j0) * HD2);

#pragma unroll
    for (int half = 0; half < 2; half++) {
        const uint4* asrc = half ? a_lo : a_hi;
        char* adst = smem + (half ? SMA_LO : SMA_HI);
#pragma unroll
        for (int it = 0; it < 8; it++) {       // A: 128 rows x 16 granules
            int idx = it * 256 + tid;
            int r = idx >> 4, g = idx & 15;
            *(uint4*)(adst + r * 256 + ((g ^ (r & 7)) << 4)) = asrc[idx];
        }
        const uint4* bsrc = half ? b_lo : b_hi;
        char* bdst = smem + (half ? SMB_LO : SMB_HI);
#pragma unroll
        for (int it = 0; it < 16; it++) {      // B: 256 rows x 16 granules
            int idx = it * 256 + tid;
            int r = idx >> 4, g = idx & 15;
            *(uint4*)(bdst + r * 256 + ((g ^ (r & 7)) << 4)) = bsrc[idx];
        }
    }
    __syncthreads();

    const uint32_t sbase = smem_u32(smem);
    const int wm = wid & 1;        // M half (64 rows)
    const int wn = wid >> 1;       // N quarter (64 cols)

    float acc[4][8][4];
#pragma unroll
    for (int mt = 0; mt < 4; mt++)
#pragma unroll
        for (int nt = 0; nt < 8; nt++)
#pragma unroll
            for (int e = 0; e < 4; e++) acc[mt][nt][e] = 0.f;

    // ldmatrix lane address components (non-trans for both operands:
    // A row-major [m,k], B = D[j,k] row-major == col-major B for row.col mma)
    const int a_rlane = (lane & 15);          // + wm*64 + mt*16
    const int a_gsel  = (lane >> 4);          // 0/1 -> k granule
    const int b_rlane = (lane & 7) + ((lane >> 4) << 3);  // + wn*64 + p*16
    const int b_gsel  = (lane >> 3) & 1;

#pragma unroll
    for (int pass = 0; pass < 3; pass++) {    // hi*hi, hi*lo, lo*hi
        const uint32_t Abase = sbase + ((pass == 2) ? SMA_LO : SMA_HI);
        const uint32_t Bbase = sbase + ((pass == 1) ? SMB_LO : SMB_HI);
#pragma unroll
        for (int kc = 0; kc < 8; kc++) {      // K = 8 x 16
            uint32_t bf[16];
#pragma unroll
            for (int p = 0; p < 4; p++) {     // 4 x ldmatrix.x4 -> 8 n-tiles
                int r = wn * 64 + p * 16 + b_rlane;
                int g = 2 * kc + b_gsel;
                ldsm_x4(&bf[p * 4], Bbase + r * 256 + ((g ^ (r & 7)) << 4));
            }
#pragma unroll
            for (int mt = 0; mt < 4; mt++) {
                int r = wm * 64 + mt * 16 + a_rlane;
                int g = 2 * kc + a_gsel;
                uint32_t af[4];
                ldsm_x4(af, Abase + r * 256 + ((g ^ (r & 7)) << 4));
#pragma unroll
                for (int nt = 0; nt < 8; nt++)
                    mma16816(acc[mt][nt], af, &bf[nt * 2]);
            }
        }
    }

    // ---- stage scores tile to SMEM (fp32, pitch 264 floats) ----
    __syncthreads();   // all ldmatrix reads done; smem reusable
    float* stage = (float*)smem;
    const int qr = lane >> 2;
    const int qc = lane & 3;
#pragma unroll
    for (int mt = 0; mt < 4; mt++)
#pragma unroll
        for (int nt = 0; nt < 8; nt++) {
            int row = wm * 64 + mt * 16 + qr;
            int cf  = wn * 64 + nt * 8 + qc * 2;
            *(float2*)&stage[row * 264 + cf] =
                make_float2(acc[mt][nt][0], acc[mt][nt][1]);
            *(float2*)&stage[(row + 8) * 264 + cf] =
                make_float2(acc[mt][nt][2], acc[mt][nt][3]);
        }
    __syncthreads();

    // ---- coalesced expansion: out[b,t,i,j] = relu(S*wh[t] + (bb*wh[t]+bh[t]))
    const float bbv = *bbp;
    float w[TT], ht[TT];
#pragma unroll
    for (int t = 0; t < TT; t++) {
        w[t]  = whp[t];
        ht[t] = fmaf(bbv, w[t], bhp[t]);
    }

#pragma unroll 1
    for (int it = 0; it < 32; it++) {
        int idx = it * 256 + tid;
        int row = idx >> 6;                   // 0..127
        int c4  = idx & 63;                   // float4 column
        float4 s = *(const float4*)&stage[row * 264 + c4 * 4];
        size_t off0 = ((size_t)(b * TT) * NN + (size_t)(i0 + row)) * NN
                    + (size_t)(j0 + c4 * 4);
#pragma unroll
        for (int t = 0; t < TT; t++) {
            float4 v;
            v.x = fmaxf(fmaf(s.x, w[t], ht[t]), 0.f);
            v.y = fmaxf(fmaf(s.y, w[t], ht[t]), 0.f);
            v.z = fmaxf(fmaf(s.z, w[t], ht[t]), 0.f);
            v.w = fmaxf(fmaf(s.w, w[t], ht[t]), 0.f);
            *(float4*)(out + off0 + (size_t)t * NN * NN) = v;
        }
    }
}

// ===========================================================================
extern "C" void kernel_launch(void* const* d_in, const int* in_sizes, int n_in,
                              void* d_out, int out_size)
{
    const float* X   = (const float*)d_in[0];
    const float* W1o = (const float*)d_in[1];
    const float* b1o = (const float*)d_in[2];
    const float* W2o = (const float*)d_in[3];
    const float* b2o = (const float*)d_in[4];
    const float* W1d = (const float*)d_in[5];
    const float* b1d = (const float*)d_in[6];
    const float* W2d = (const float*)d_in[7];
    const float* b2d = (const float*)d_in[8];
    const float* Wb  = (const float*)d_in[9];
    const float* bb  = (const float*)d_in[10];
    const float* wh  = (const float*)d_in[11];
    const float* bh  = (const float*)d_in[12];
    float* out = (float*)d_out;

    static bool attr_set = false;
    if (!attr_set) {
        cudaFuncSetAttribute(scores_mma_kernel,
                             cudaFuncAttributeMaxDynamicSharedMemorySize, SM_TOTAL);
        attr_set = true;
    }

    // Fold Wb into the o-path second layer
    fuse_w_kernel<<<HH, HD2>>>(W2o, b2o, Wb);

    // Stage 0: H1o/H1d = relu(X @ W1{o,d} + b1{o,d})
    gemm_stage0_kernel<<<dim3(HH / 64, MTOT / 128, 2), 256>>>(X, W1o, W1d, b1o, b1d);

    // Stage 1: OW/D (emitted as bf16 hi/lo splits)
    gemm_stage1_kernel<<<dim3(HD2 / 64, MTOT / 128, 2), 256>>>(W2d, b2d);

    // Tensor-core scores GEMM + horizon expansion -> (B,T,N,N)
    scores_mma_kernel<<<dim3(NN / 256, NN / 128, NB), 256, SM_TOTAL>>>(bb, wh, bh, out);
}